// round 3
// baseline (speedup 1.0000x reference)
#include <cuda_runtime.h>
#include <cstdint>
#include <cstddef>

#define B_ 16
#define L_ 16384
#define C_ 256
#define NH 8
#define HD 32
#define FFN 512
#define EPS 1e-5f
#define SCALE_ATT 0.17677669529663687f

#define NCH 64      // chunks per batch
#define RPC 256     // rows per chunk
#define TR 64       // tile rows
#define NT 4        // tiles per chunk
#define KB 32       // k-tile depth
#define QKP_ST 260  // padded qkp row stride (bank-conflict avoidance)

typedef unsigned long long ull;

// ---------------- device scratch (static, no allocations) ----------------
__device__ float g_qkp[B_ * NH * C_];            // scale-folded q @ Wk per head
__device__ float g_qb[B_ * NH];                  // scale-folded q . bk per head
__device__ float g_pmax[B_ * NCH * NH];
__device__ float g_psum[B_ * NCH * NH];
__device__ float g_pctx[(size_t)B_ * NCH * NH * C_];   // 8 MB partial contexts

// ---------------- helpers ----------------
union F4 { float4 v; ull u[2]; };

__device__ __forceinline__ void ffma2(ull& d, ull a, ull b) {
    asm("fma.rn.f32x2 %0, %1, %2, %0;" : "+l"(d) : "l"(a), "l"(b));
}
__device__ __forceinline__ void mul2(ull& d, ull a) {
    asm("mul.rn.f32x2 %0, %0, %1;" : "+l"(d) : "l"(a));
}
__device__ __forceinline__ ull pack2(float x) {
    ull r; unsigned int u = __float_as_uint(x);
    asm("mov.b64 %0, {%1, %1};" : "=l"(r) : "r"(u));
    return r;
}
__device__ __forceinline__ float2 unpack2(ull v) {
    unsigned int lo, hi;
    asm("mov.b64 {%0, %1}, %2;" : "=r"(lo), "=r"(hi) : "l"(v));
    return make_float2(__uint_as_float(lo), __uint_as_float(hi));
}

// ============================================================
// K0: q = LN(query) @ W_q + b_q ; fold into qkp[b,h,c], qb[b,h]
// grid 16 (batch), 256 threads
// ============================================================
__global__ void k0_query(const float* __restrict__ query,
                         const float* __restrict__ W_q,  const float* __restrict__ b_q,
                         const float* __restrict__ W_kv, const float* __restrict__ b_kv,
                         const float* __restrict__ g_q,  const float* __restrict__ be_q)
{
    __shared__ float qn[C_], qs[C_], red[8], red2[8];
    const int b = blockIdx.x, t = threadIdx.x;

    float x = query[b * C_ + t];
    float s = x, s2 = x * x;
    #pragma unroll
    for (int o = 16; o >= 1; o >>= 1) {
        s  += __shfl_xor_sync(0xffffffffu, s,  o);
        s2 += __shfl_xor_sync(0xffffffffu, s2, o);
    }
    if ((t & 31) == 0) { red[t >> 5] = s; red2[t >> 5] = s2; }
    __syncthreads();
    float sum = 0.f, sumsq = 0.f;
    #pragma unroll
    for (int i = 0; i < 8; i++) { sum += red[i]; sumsq += red2[i]; }
    float mean = sum * (1.f / C_);
    float var  = sumsq * (1.f / C_) - mean * mean;
    float rs   = rsqrtf(var + EPS);
    qn[t] = (x - mean) * rs * g_q[t] + be_q[t];
    __syncthreads();

    float qj = b_q[t];
    for (int c = 0; c < C_; c++) qj += qn[c] * W_q[c * C_ + t];
    qs[t] = qj;
    __syncthreads();

    // qkp[b][h][c=t] = scale * sum_d qs[h*32+d] * W_kv[c][h*32+d]
    float a[NH];
    #pragma unroll
    for (int h = 0; h < NH; h++) a[h] = 0.f;
    const float* wrow = W_kv + (size_t)t * (2 * C_);
    #pragma unroll
    for (int h = 0; h < NH; h++) {
        float acc = 0.f;
        #pragma unroll 8
        for (int d = 0; d < HD; d++) acc += qs[h * HD + d] * wrow[h * HD + d];
        a[h] = acc;
    }
    #pragma unroll
    for (int h = 0; h < NH; h++)
        g_qkp[(b * NH + h) * C_ + t] = a[h] * SCALE_ATT;

    if (t < NH) {
        float qb = 0.f;
        #pragma unroll 8
        for (int d = 0; d < HD; d++) qb += qs[t * HD + d] * b_kv[t * HD + d];
        g_qb[b * NH + t] = qb * SCALE_ATT;
    }
}

// ============================================================
// K1: main fused kernel — m = LN(relu(mem@W_ip+b)), scores, online
// softmax, context accumulation. grid 1024 (b*64+chunk), 256 thr.
// ============================================================
struct SmemK1 {
    union {
        struct { float As[TR * KB]; float Bs[KB * C_]; } g;   // 40 KB
        float msm[TR * C_];                                    // 64 KB
    } u;
    float qkp[NH * QKP_ST];   // 8320 B
    float ctx[NH * C_];       // 8 KB
    float bip[C_], gip[C_], bei[C_];
    float ssm[NH * TR], wsm[NH * TR], iorsm[NH * TR];
    float qb[NH];
    float rmax[NH], rsum[NH], fsc[NH];
};

__global__ void __launch_bounds__(256, 2)
k1_main(const float* __restrict__ mem,  const float* __restrict__ ior,
        const float* __restrict__ W_ip, const float* __restrict__ b_ip,
        const float* __restrict__ g_ip, const float* __restrict__ be_ip)
{
    extern __shared__ char smraw[];
    SmemK1& S = *reinterpret_cast<SmemK1*>(smraw);
    const int t = threadIdx.x;
    const int b = blockIdx.x >> 6;
    const int ch = blockIdx.x & 63;
    const int trow = t >> 5, tcol = t & 31;

    // ---- per-block init ----
    for (int i = t; i < NH * C_; i += 256) {
        S.ctx[i] = 0.f;
        int h = i >> 8, c = i & 255;
        S.qkp[h * QKP_ST + c] = g_qkp[(b * NH + h) * C_ + c];
    }
    S.bip[t] = b_ip[t]; S.gip[t] = g_ip[t]; S.bei[t] = be_ip[t];
    if (t < NH) {
        S.qb[t]   = g_qb[b * NH + t];
        S.rmax[t] = -1e30f;
        S.rsum[t] = 0.f;
    }

    const float4* Am   = (const float4*)(mem + (size_t)(b * L_ + ch * RPC) * C_);
    const float4* Wip4 = (const float4*)W_ip;
    float4* As4 = (float4*)S.u.g.As;
    float4* Bs4 = (float4*)S.u.g.Bs;

    for (int tile = 0; tile < NT; tile++) {
        // ---- ior slab for this tile: [8 heads][64 rows] ----
        {
            const int base = ch * RPC + tile * TR;
            int i0 = t, i1 = t + 256;
            S.iorsm[i0] = ior[(b * NH + (i0 >> 6)) * L_ + base + (i0 & 63)];
            S.iorsm[i1] = ior[(b * NH + (i1 >> 6)) * L_ + base + (i1 & 63)];
        }

        // ---- GEMM: mtile[64,256] = mem_tile @ W_ip (f32x2) ----
        ull acc[8][4];
        #pragma unroll
        for (int r = 0; r < 8; r++)
            #pragma unroll
            for (int j = 0; j < 4; j++) acc[r][j] = 0ULL;

        for (int kt = 0; kt < C_ / KB; kt++) {
            __syncthreads();
            #pragma unroll
            for (int i = 0; i < 2; i++) {
                int f = t + i * 256;                    // f = row*8 + kv
                As4[f] = Am[(tile * TR + (f >> 3)) * 64 + kt * 8 + (f & 7)];
            }
            #pragma unroll
            for (int i = 0; i < 8; i++) {
                int f = t + i * 256;                    // f = kk*64 + c4
                Bs4[f] = Wip4[(kt * KB + (f >> 6)) * 64 + (f & 63)];
            }
            __syncthreads();
            #pragma unroll 8
            for (int kk = 0; kk < KB; kk++) {
                F4 b0, b1;
                b0.v = Bs4[kk * 64 + tcol];         // cols tcol*4 .. +3
                b1.v = Bs4[kk * 64 + 32 + tcol];    // cols 128+tcol*4 .. +3
                #pragma unroll
                for (int r = 0; r < 8; r++) {
                    ull ap = pack2(S.u.g.As[(trow * 8 + r) * KB + kk]);  // broadcast
                    ffma2(acc[r][0], ap, b0.u[0]);
                    ffma2(acc[r][1], ap, b0.u[1]);
                    ffma2(acc[r][2], ap, b1.u[0]);
                    ffma2(acc[r][3], ap, b1.u[1]);
                }
            }
        }
        __syncthreads();   // all As/Bs reads done; msm may overwrite union

        // ---- epilogue: bias + relu + LayerNorm -> msm ----
        {
            float bf[8], gf[8], ef[8];
            const float4* bip4 = (const float4*)S.bip;
            const float4* gip4 = (const float4*)S.gip;
            const float4* bei4 = (const float4*)S.bei;
            *(float4*)&bf[0] = bip4[tcol]; *(float4*)&bf[4] = bip4[32 + tcol];
            *(float4*)&gf[0] = gip4[tcol]; *(float4*)&gf[4] = gip4[32 + tcol];
            *(float4*)&ef[0] = bei4[tcol]; *(float4*)&ef[4] = bei4[32 + tcol];

            #pragma unroll
            for (int i = 0; i < 8; i++) {
                int row = trow * 8 + i;
                float v[8]; float2 p;
                p = unpack2(acc[i][0]); v[0] = p.x; v[1] = p.y;
                p = unpack2(acc[i][1]); v[2] = p.x; v[3] = p.y;
                p = unpack2(acc[i][2]); v[4] = p.x; v[5] = p.y;
                p = unpack2(acc[i][3]); v[6] = p.x; v[7] = p.y;
                float sum = 0.f, sumsq = 0.f;
                #pragma unroll
                for (int j = 0; j < 8; j++) {
                    float x = fmaxf(v[j] + bf[j], 0.f);
                    v[j] = x; sum += x; sumsq += x * x;
                }
                #pragma unroll
                for (int o = 16; o >= 1; o >>= 1) {
                    sum   += __shfl_xor_sync(0xffffffffu, sum,   o);
                    sumsq += __shfl_xor_sync(0xffffffffu, sumsq, o);
                }
                float mean = sum * (1.f / C_);
                float var  = sumsq * (1.f / C_) - mean * mean;
                float rs   = rsqrtf(var + EPS);
                float o0[4], o1[4];
                #pragma unroll
                for (int j = 0; j < 4; j++) o0[j] = (v[j] - mean) * rs * gf[j] + ef[j];
                #pragma unroll
                for (int j = 0; j < 4; j++) o1[j] = (v[4 + j] - mean) * rs * gf[4 + j] + ef[4 + j];
                float4* d = (float4*)&S.u.msm[row * C_];
                d[tcol]      = make_float4(o0[0], o0[1], o0[2], o0[3]);
                d[32 + tcol] = make_float4(o1[0], o1[1], o1[2], o1[3]);
            }
        }
        __syncthreads();

        // ---- scores: ssm[h][r] = (m_r . qkp_h + qb_h) * ior ----
        {
            const int h = t & 7, r0 = t >> 3;     // r0 in 0..31
            #pragma unroll
            for (int half = 0; half < 2; half++) {
                int r = r0 + half * 32;
                const float4* mr = (const float4*)&S.u.msm[r * C_];
                const float4* qr = (const float4*)&S.qkp[h * QKP_ST];
                float a = 0.f;
                #pragma unroll 8
                for (int c4 = 0; c4 < 64; c4++) {
                    float4 mv = mr[c4], qv = qr[c4];
                    a += mv.x * qv.x + mv.y * qv.y + mv.z * qv.z + mv.w * qv.w;
                }
                S.ssm[h * TR + r] = (a + S.qb[h]) * S.iorsm[h * TR + r];
            }
        }
        __syncthreads();

        // ---- online softmax update (warp w handles head w) ----
        {
            const int w = t >> 5, lane = t & 31;
            float s0 = S.ssm[w * TR + lane], s1 = S.ssm[w * TR + 32 + lane];
            float mx = fmaxf(s0, s1);
            #pragma unroll
            for (int o = 16; o >= 1; o >>= 1)
                mx = fmaxf(mx, __shfl_xor_sync(0xffffffffu, mx, o));
            float om = S.rmax[w];
            float nm = fmaxf(om, mx);
            float e0 = __expf(s0 - nm), e1 = __expf(s1 - nm);
            S.wsm[w * TR + lane]      = e0;
            S.wsm[w * TR + 32 + lane] = e1;
            float es = e0 + e1;
            #pragma unroll
            for (int o = 16; o >= 1; o >>= 1)
                es += __shfl_xor_sync(0xffffffffu, es, o);
            if (lane == 0) {
                float f = __expf(om - nm);
                S.fsc[w]  = f;
                S.rsum[w] = S.rsum[w] * f + es;
                S.rmax[w] = nm;
            }
        }
        __syncthreads();

        // ---- context accumulate: ctx[h][c] = ctx*f + sum_r w[r]*m[r][c] ----
        {
            const int h = t >> 5, c04 = (t & 31) * 2;   // float4 idx, cols (t&31)*8
            float4* ctx4 = (float4*)&S.ctx[h * C_];
            F4 c0u, c1u;
            c0u.v = ctx4[c04]; c1u.v = ctx4[c04 + 1];
            ull fp = pack2(S.fsc[h]);
            ull cx0 = c0u.u[0], cx1 = c0u.u[1], cx2 = c1u.u[0], cx3 = c1u.u[1];
            mul2(cx0, fp); mul2(cx1, fp); mul2(cx2, fp); mul2(cx3, fp);
            #pragma unroll 8
            for (int r = 0; r < TR; r++) {
                ull wp = pack2(S.wsm[h * TR + r]);
                const float4* mr = (const float4*)&S.u.msm[r * C_];
                F4 m0, m1; m0.v = mr[c04]; m1.v = mr[c04 + 1];
                ffma2(cx0, wp, m0.u[0]);
                ffma2(cx1, wp, m0.u[1]);
                ffma2(cx2, wp, m1.u[0]);
                ffma2(cx3, wp, m1.u[1]);
            }
            F4 o0, o1;
            o0.u[0] = cx0; o0.u[1] = cx1; o1.u[0] = cx2; o1.u[1] = cx3;
            ctx4[c04] = o0.v; ctx4[c04 + 1] = o1.v;
        }
        // loop-entry syncthreads guards the msm/As/Bs union for next tile
    }

    __syncthreads();
    // ---- write partials ----
    for (int i = t; i < NH * C_; i += 256)
        g_pctx[(size_t)blockIdx.x * (NH * C_) + i] = S.ctx[i];
    if (t < NH) {
        g_pmax[blockIdx.x * NH + t] = S.rmax[t];
        g_psum[blockIdx.x * NH + t] = S.rsum[t];
    }
}

// ============================================================
// K2: combine partials, V-projection, residual, LN, FFN (exact GELU)
// grid 16 (batch), 256 threads
// ============================================================
__global__ void k2_final(const float* __restrict__ query,
                         const float* __restrict__ W_kv, const float* __restrict__ b_kv,
                         const float* __restrict__ g_f,  const float* __restrict__ be_f,
                         const float* __restrict__ W1,   const float* __restrict__ b1,
                         const float* __restrict__ W2,   const float* __restrict__ b2,
                         float* __restrict__ out)
{
    __shared__ float pm[NCH * NH], ps[NCH * NH], gm[NH], gs[NH];
    __shared__ float ctxn[NH * C_];
    __shared__ float xs[C_], hs[C_], us[FFN];
    __shared__ float red[8], red2[8];
    const int b = blockIdx.x, t = threadIdx.x;

    for (int i = t; i < NCH * NH; i += 256) {
        pm[i] = g_pmax[b * NCH * NH + i];
        ps[i] = g_psum[b * NCH * NH + i];
    }
    __syncthreads();

    // global max / sum per head (warp w = head w; lanes cover 2 chunks each)
    {
        const int w = t >> 5, lane = t & 31;
        float a = pm[lane * NH + w], c = pm[(lane + 32) * NH + w];
        float mx = fmaxf(a, c);
        #pragma unroll
        for (int o = 16; o >= 1; o >>= 1)
            mx = fmaxf(mx, __shfl_xor_sync(0xffffffffu, mx, o));
        float sm = ps[lane * NH + w] * __expf(a - mx)
                 + ps[(lane + 32) * NH + w] * __expf(c - mx);
        #pragma unroll
        for (int o = 16; o >= 1; o >>= 1)
            sm += __shfl_xor_sync(0xffffffffu, sm, o);
        if (lane == 0) { gm[w] = mx; gs[w] = sm; }
    }
    __syncthreads();

    // combine contexts
    {
        const int h = t >> 5, c0 = (t & 31) * 8;
        float a[8];
        #pragma unroll
        for (int j = 0; j < 8; j++) a[j] = 0.f;
        for (int chh = 0; chh < NCH; chh++) {
            float f = __expf(pm[chh * NH + h] - gm[h]);
            const float4* p = (const float4*)&g_pctx[((size_t)(b * NCH + chh) * NH + h) * C_ + c0];
            float4 v0 = p[0], v1 = p[1];
            a[0] += f * v0.x; a[1] += f * v0.y; a[2] += f * v0.z; a[3] += f * v0.w;
            a[4] += f * v1.x; a[5] += f * v1.y; a[6] += f * v1.z; a[7] += f * v1.w;
        }
        float inv = 1.f / gs[h];
        #pragma unroll
        for (int j = 0; j < 8; j++) ctxn[h * C_ + c0 + j] = a[j] * inv;
    }
    __syncthreads();

    // V projection + residual + LN
    {
        const int h = t >> 5;
        float o = b_kv[C_ + t];
        for (int c = 0; c < C_; c++) o += ctxn[h * C_ + c] * W_kv[c * (2 * C_) + C_ + t];
        float x = o + query[b * C_ + t];
        xs[t] = x;
        float s = x, s2 = x * x;
        #pragma unroll
        for (int o2 = 16; o2 >= 1; o2 >>= 1) {
            s  += __shfl_xor_sync(0xffffffffu, s,  o2);
            s2 += __shfl_xor_sync(0xffffffffu, s2, o2);
        }
        if ((t & 31) == 0) { red[t >> 5] = s; red2[t >> 5] = s2; }
        __syncthreads();
        float sum = 0.f, sumsq = 0.f;
        #pragma unroll
        for (int i = 0; i < 8; i++) { sum += red[i]; sumsq += red2[i]; }
        float mean = sum * (1.f / C_);
        float var  = sumsq * (1.f / C_) - mean * mean;
        float rs   = rsqrtf(var + EPS);
        hs[t] = (x - mean) * rs * g_f[t] + be_f[t];
    }
    __syncthreads();

    // FFN layer 1 + exact GELU
    for (int f = t; f < FFN; f += 256) {
        float u = b1[f];
        for (int c = 0; c < C_; c++) u += hs[c] * W1[c * FFN + f];
        us[f] = 0.5f * u * (1.f + erff(u * 0.70710678118654752f));
    }
    __syncthreads();

    // FFN layer 2 + residual
    {
        float y = b2[t];
        for (int f = 0; f < FFN; f++) y += us[f] * W2[f * C_ + t];
        out[b * C_ + t] = xs[t] + y;
    }
}

// ============================================================
extern "C" void kernel_launch(void* const* d_in, const int* in_sizes, int n_in,
                              void* d_out, int out_size)
{
    const float* query = (const float*)d_in[0];
    const float* mem   = (const float*)d_in[1];
    const float* ior   = (const float*)d_in[2];
    const float* W_ip  = (const float*)d_in[3];
    const float* b_ip  = (const float*)d_in[4];
    const float* g_ip  = (const float*)d_in[5];
    const float* be_ip = (const float*)d_in[6];
    const float* W_q   = (const float*)d_in[7];
    const float* b_q   = (const float*)d_in[8];
    const float* W_kv  = (const float*)d_in[9];
    const float* b_kv  = (const float*)d_in[10];
    const float* g_q   = (const float*)d_in[11];
    const float* be_q  = (const float*)d_in[12];
    const float* g_f   = (const float*)d_in[13];
    const float* be_f  = (const float*)d_in[14];
    const float* W1    = (const float*)d_in[15];
    const float* b1    = (const float*)d_in[16];
    const float* W2    = (const float*)d_in[17];
    const float* b2    = (const float*)d_in[18];
    float* out = (float*)d_out;

    const int smem = (int)sizeof(SmemK1);
    cudaFuncSetAttribute(k1_main, cudaFuncAttributeMaxDynamicSharedMemorySize, smem);

    k0_query<<<B_, 256>>>(query, W_q, b_q, W_kv, b_kv, g_q, be_q);
    k1_main<<<B_ * NCH, 256, smem>>>(mem, ior, W_ip, b_ip, g_ip, be_ip);
    k2_final<<<B_, 256>>>(query, W_kv, b_kv, g_f, be_f, W1, b1, W2, b2, out);
}

// round 5
// speedup vs baseline: 1.7383x; 1.7383x over previous
#include <cuda_runtime.h>
#include <cuda_bf16.h>
#include <cstdint>
#include <cstddef>

#define B_ 16
#define L_ 16384
#define C_ 256
#define NH 8
#define FFN 512
#define EPS 1e-5f
#define SCALE_ATT 0.17677669529663687f
#define JOBS 2048

// k1 smem byte offsets
#define O_AH 0
#define O_AL 10240
#define O_B0 20480      /* double buffer: 2 x (hi 20480 + lo 20480) */
#define O_MSM 0         /* fp32 [128][260], overlays GEMM bufs, 133120 B */
#define O_SPC 133120    /* 32768: score partials then ctx partials */
#define O_QKP 165888    /* 4 replicas x 2116 floats (8464 B) */
#define O_IOR 199744
#define O_WSM 203840
#define O_ST  207936
#define O_QB  209984
#define O_BIP 210016
#define O_GIP 211040
#define O_BEI 212064
#define SM1   213088

__device__ float g_qkp[B_ * NH * C_];
__device__ float g_qb[B_ * NH];
__device__ float g_pmax[JOBS * NH];
__device__ float g_psum[JOBS * NH];
__device__ float g_pctx[(size_t)JOBS * NH * C_];
__device__ __align__(16) __nv_bfloat16 g_wh[C_ * C_];   // W_ip^T hi, n-major
__device__ __align__(16) __nv_bfloat16 g_wl[C_ * C_];   // W_ip^T lo, n-major

__device__ __forceinline__ uint32_t smem_u32(const void* p) {
    uint32_t a;
    asm("{ .reg .u64 t; cvta.to.shared.u64 t, %1; cvt.u32.u64 %0, t; }" : "=r"(a) : "l"(p));
    return a;
}
__device__ __forceinline__ void ldmx4(uint32_t* r, uint32_t a) {
    asm volatile("ldmatrix.sync.aligned.m8n8.x4.shared.b16 {%0,%1,%2,%3}, [%4];"
        : "=r"(r[0]), "=r"(r[1]), "=r"(r[2]), "=r"(r[3]) : "r"(a));
}
__device__ __forceinline__ void mma16816(float* d, const uint32_t* a, uint32_t b0, uint32_t b1) {
    asm volatile("mma.sync.aligned.m16n8k16.row.col.f32.bf16.bf16.f32 "
        "{%0,%1,%2,%3}, {%4,%5,%6,%7}, {%8,%9}, {%0,%1,%2,%3};"
        : "+f"(d[0]), "+f"(d[1]), "+f"(d[2]), "+f"(d[3])
        : "r"(a[0]), "r"(a[1]), "r"(a[2]), "r"(a[3]), "r"(b0), "r"(b1));
}
#define CPA(dst, src) asm volatile("cp.async.cg.shared.global [%0], [%1], 16;" :: "r"(dst), "l"(src))
#define CPC() asm volatile("cp.async.commit_group;" ::: "memory")
#define CPW(n) asm volatile("cp.async.wait_group %0;" :: "n"(n) : "memory")

// ---- K0b: split W_ip^T into bf16 hi/lo, n-major ----
__global__ void k0b(const float* __restrict__ W_ip) {
    const int n = blockIdx.x, k = threadIdx.x;
    float w = W_ip[k * C_ + n];
    __nv_bfloat16 hi = __float2bfloat16(w);
    g_wh[n * C_ + k] = hi;
    g_wl[n * C_ + k] = __float2bfloat16(w - __bfloat162float(hi));
}

// ---- K0: fold LN(query)@W_q into qkp/qb ----
__global__ void k0(const float* __restrict__ query, const float* __restrict__ W_q,
                   const float* __restrict__ b_q, const float* __restrict__ W_kv,
                   const float* __restrict__ b_kv, const float* __restrict__ g_q,
                   const float* __restrict__ be_q) {
    __shared__ float qn[C_], qs[C_], red[8], red2[8];
    const int b = blockIdx.x, t = threadIdx.x;
    float x = query[b * C_ + t];
    float s = x, s2 = x * x;
    #pragma unroll
    for (int o = 16; o >= 1; o >>= 1) {
        s += __shfl_xor_sync(~0u, s, o);
        s2 += __shfl_xor_sync(~0u, s2, o);
    }
    if ((t & 31) == 0) { red[t >> 5] = s; red2[t >> 5] = s2; }
    __syncthreads();
    float su = 0.f, sq = 0.f;
    #pragma unroll
    for (int i = 0; i < 8; i++) { su += red[i]; sq += red2[i]; }
    float mean = su / C_, var = sq / C_ - mean * mean, rs = rsqrtf(var + EPS);
    qn[t] = (x - mean) * rs * g_q[t] + be_q[t];
    __syncthreads();
    float a0 = 0.f, a1 = 0.f, a2 = 0.f, a3 = 0.f;
    #pragma unroll 8
    for (int c = 0; c < C_; c += 4) {
        a0 += qn[c] * W_q[c * C_ + t];
        a1 += qn[c + 1] * W_q[(c + 1) * C_ + t];
        a2 += qn[c + 2] * W_q[(c + 2) * C_ + t];
        a3 += qn[c + 3] * W_q[(c + 3) * C_ + t];
    }
    qs[t] = b_q[t] + (a0 + a1) + (a2 + a3);
    __syncthreads();
    const float* wr = W_kv + (size_t)t * (2 * C_);
    #pragma unroll
    for (int h = 0; h < NH; h++) {
        float acc = 0.f;
        #pragma unroll 8
        for (int d = 0; d < 32; d++) acc += qs[h * 32 + d] * wr[h * 32 + d];
        g_qkp[(b * NH + h) * C_ + t] = acc * SCALE_ATT;
    }
    if (t < NH) {
        float qb = 0.f;
        #pragma unroll 8
        for (int d = 0; d < 32; d++) qb += qs[t * 32 + d] * b_kv[t * 32 + d];
        g_qb[b * NH + t] = qb * SCALE_ATT;
    }
}

// ---- K1: HMMA fused main kernel (one 128-row tile per block) ----
__global__ void __launch_bounds__(512, 1)
k1(const float* __restrict__ mem, const float* __restrict__ ior,
   const float* __restrict__ b_ip, const float* __restrict__ g_ip,
   const float* __restrict__ be_ip) {
    extern __shared__ char sm[];
    float* S = (float*)sm;
    const uint32_t smb = smem_u32(sm);
    const int t = threadIdx.x, lane = t & 31, wid = t >> 5;
    const int rg = wid >> 1, cg = wid & 1;
    const int j = blockIdx.x, b = j >> 7, row0 = (j & 127) << 7;

    // per-block init
    for (int i = t; i < NH * C_; i += 512) {
        float v = g_qkp[b * NH * C_ + i];
        int h = i >> 8, c = i & 255;
        #pragma unroll
        for (int q = 0; q < 4; q++)
            S[(O_QKP >> 2) + q * 2116 + h * 264 + c] = v;
    }
    if (t < NH) S[(O_QB >> 2) + t] = g_qb[b * NH + t];
    for (int i = t; i < NH * 128; i += 512)
        S[(O_IOR >> 2) + i] = ior[(size_t)(b * NH + (i >> 7)) * L_ + row0 + (i & 127)];
    if (t < C_) {
        S[(O_BIP >> 2) + t] = b_ip[t];
        S[(O_GIP >> 2) + t] = g_ip[t];
        S[(O_BEI >> 2) + t] = be_ip[t];
    }

    // ---- GEMM: [128,256] = A[128,256] @ B^T, bf16 split x3, K-chunks of 32 ----
    const float4* mem4 = (const float4*)mem;
    const int ar = t >> 2, aq = t & 3;
    const size_t abase = (size_t)(b * L_ + row0 + ar) * 64;
    float4 av0 = mem4[abase + aq * 2], av1 = mem4[abase + aq * 2 + 1];

    const int bn = t >> 1, bf = t & 1;
    {
        const char* sH = (const char*)g_wh + ((size_t)bn * 256 + bf * 16) * 2;
        const char* sL = (const char*)g_wl + ((size_t)bn * 256 + bf * 16) * 2;
        uint32_t d0 = smb + O_B0 + bn * 80 + bf * 32;
        CPA(d0, sH); CPA(d0 + 16, sH + 16);
        CPA(d0 + 20480, sL); CPA(d0 + 20480 + 16, sL + 16);
        CPC();
    }

    float d[16][4];
    #pragma unroll
    for (int i = 0; i < 16; i++)
        #pragma unroll
        for (int q = 0; q < 4; q++) d[i][q] = 0.f;

    const int lg = lane >> 3, lr = lane & 7;
    const uint32_t aAddr = smb + O_AH + (rg * 16 + ((lg & 1) << 3) + lr) * 80 + (lg >> 1) * 16;
    const uint32_t bOff = (cg * 128 + ((lg >> 1) << 3) + lr) * 80 + (lg & 1) * 16;

    for (int kc = 0; kc < 8; kc++) {
        __syncthreads();
        {   // A regs -> smem (split hi/lo)
            __nv_bfloat162 h0 = __floats2bfloat162_rn(av0.x, av0.y);
            __nv_bfloat162 h1 = __floats2bfloat162_rn(av0.z, av0.w);
            __nv_bfloat162 h2 = __floats2bfloat162_rn(av1.x, av1.y);
            __nv_bfloat162 h3 = __floats2bfloat162_rn(av1.z, av1.w);
            __nv_bfloat162 l0 = __floats2bfloat162_rn(av0.x - __bfloat162float(h0.x),
                                                      av0.y - __bfloat162float(h0.y));
            __nv_bfloat162 l1 = __floats2bfloat162_rn(av0.z - __bfloat162float(h1.x),
                                                      av0.w - __bfloat162float(h1.y));
            __nv_bfloat162 l2 = __floats2bfloat162_rn(av1.x - __bfloat162float(h2.x),
                                                      av1.y - __bfloat162float(h2.y));
            __nv_bfloat162 l3 = __floats2bfloat162_rn(av1.z - __bfloat162float(h3.x),
                                                      av1.w - __bfloat162float(h3.y));
            int ao = ar * 80 + aq * 16;
            *(uint4*)(sm + O_AH + ao) = make_uint4(*(uint32_t*)&h0, *(uint32_t*)&h1,
                                                   *(uint32_t*)&h2, *(uint32_t*)&h3);
            *(uint4*)(sm + O_AL + ao) = make_uint4(*(uint32_t*)&l0, *(uint32_t*)&l1,
                                                   *(uint32_t*)&l2, *(uint32_t*)&l3);
        }
        if (kc < 7) {
            av0 = mem4[abase + (kc + 1) * 8 + aq * 2];
            av1 = mem4[abase + (kc + 1) * 8 + aq * 2 + 1];
            const char* sH = (const char*)g_wh + ((size_t)bn * 256 + (kc + 1) * 32 + bf * 16) * 2;
            const char* sL = (const char*)g_wl + ((size_t)bn * 256 + (kc + 1) * 32 + bf * 16) * 2;
            uint32_t d0 = smb + O_B0 + ((kc + 1) & 1) * 40960 + bn * 80 + bf * 32;
            CPA(d0, sH); CPA(d0 + 16, sH + 16);
            CPA(d0 + 20480, sL); CPA(d0 + 20480 + 16, sL + 16);
            CPC();
            CPW(1);
        } else {
            CPW(0);
        }
        __syncthreads();

        uint32_t bufB = smb + O_B0 + (kc & 1) * 40960 + bOff;
        #pragma unroll
        for (int ks = 0; ks < 2; ks++) {
            uint32_t ah[4], al[4];
            ldmx4(ah, aAddr + ks * 32);
            ldmx4(al, aAddr + (O_AL - O_AH) + ks * 32);
            #pragma unroll
            for (int jt = 0; jt < 8; jt++) {
                uint32_t bh[4], bl[4];
                ldmx4(bh, bufB + jt * 1280 + ks * 32);
                ldmx4(bl, bufB + 20480 + jt * 1280 + ks * 32);
                mma16816(d[2 * jt], ah, bh[0], bh[1]);
                mma16816(d[2 * jt], al, bh[0], bh[1]);
                mma16816(d[2 * jt], ah, bl[0], bl[1]);
                mma16816(d[2 * jt + 1], ah, bh[2], bh[3]);
                mma16816(d[2 * jt + 1], al, bh[2], bh[3]);
                mma16816(d[2 * jt + 1], ah, bl[2], bl[3]);
            }
        }
    }
    __syncthreads();   // all ldmatrix reads done; msm may overwrite GEMM bufs

    // ---- epilogue ----
    const int r0 = rg * 16 + (lane >> 2), r1 = r0 + 8;
    const int cq = (lane & 3) * 2;

    float s0 = 0.f, q0 = 0.f, s1 = 0.f, q1 = 0.f;
    #pragma unroll
    for (int nt = 0; nt < 16; nt++) {
        int c = cg * 128 + nt * 8 + cq;
        float2 bb = *(float2*)&S[(O_BIP >> 2) + c];
        float x0 = fmaxf(d[nt][0] + bb.x, 0.f), x1 = fmaxf(d[nt][1] + bb.y, 0.f);
        float y0 = fmaxf(d[nt][2] + bb.x, 0.f), y1 = fmaxf(d[nt][3] + bb.y, 0.f);
        d[nt][0] = x0; d[nt][1] = x1; d[nt][2] = y0; d[nt][3] = y1;
        s0 += x0 + x1; q0 += x0 * x0 + x1 * x1;
        s1 += y0 + y1; q1 += y0 * y0 + y1 * y1;
    }
    #pragma unroll
    for (int o = 1; o <= 2; o <<= 1) {
        s0 += __shfl_xor_sync(~0u, s0, o); q0 += __shfl_xor_sync(~0u, q0, o);
        s1 += __shfl_xor_sync(~0u, s1, o); q1 += __shfl_xor_sync(~0u, q1, o);
    }
    if ((lane & 3) == 0) {
        S[(O_ST >> 2) + r0 * 2 + cg] = s0; S[(O_ST >> 2) + 256 + r0 * 2 + cg] = q0;
        S[(O_ST >> 2) + r1 * 2 + cg] = s1; S[(O_ST >> 2) + 256 + r1 * 2 + cg] = q1;
    }
    __syncthreads();
    float mean0, rs0, mean1, rs1;
    {
        float su = S[(O_ST >> 2) + r0 * 2] + S[(O_ST >> 2) + r0 * 2 + 1];
        float sq = S[(O_ST >> 2) + 256 + r0 * 2] + S[(O_ST >> 2) + 256 + r0 * 2 + 1];
        mean0 = su / C_; rs0 = rsqrtf(sq / C_ - mean0 * mean0 + EPS);
        su = S[(O_ST >> 2) + r1 * 2] + S[(O_ST >> 2) + r1 * 2 + 1];
        sq = S[(O_ST >> 2) + 256 + r1 * 2] + S[(O_ST >> 2) + 256 + r1 * 2 + 1];
        mean1 = su / C_; rs1 = rsqrtf(sq / C_ - mean1 * mean1 + EPS);
    }

    float p0[NH], p1[NH];
    #pragma unroll
    for (int h = 0; h < NH; h++) { p0[h] = 0.f; p1[h] = 0.f; }
    const int qrep = (O_QKP >> 2) + (lane & 3) * 2116;
    #pragma unroll
    for (int nt = 0; nt < 16; nt++) {
        int c = cg * 128 + nt * 8 + cq;
        float2 gg = *(float2*)&S[(O_GIP >> 2) + c];
        float2 ee = *(float2*)&S[(O_BEI >> 2) + c];
        float v00 = (d[nt][0] - mean0) * rs0 * gg.x + ee.x;
        float v01 = (d[nt][1] - mean0) * rs0 * gg.y + ee.y;
        float v10 = (d[nt][2] - mean1) * rs1 * gg.x + ee.x;
        float v11 = (d[nt][3] - mean1) * rs1 * gg.y + ee.y;
        *(float2*)&S[(O_MSM >> 2) + r0 * 260 + c] = make_float2(v00, v01);
        *(float2*)&S[(O_MSM >> 2) + r1 * 260 + c] = make_float2(v10, v11);
        #pragma unroll
        for (int h = 0; h < NH; h++) {
            float2 qv = *(float2*)&S[qrep + h * 264 + c];
            p0[h] += v00 * qv.x + v01 * qv.y;
            p1[h] += v10 * qv.x + v11 * qv.y;
        }
    }
    #pragma unroll
    for (int o = 1; o <= 2; o <<= 1)
        #pragma unroll
        for (int h = 0; h < NH; h++) {
            p0[h] += __shfl_xor_sync(~0u, p0[h], o);
            p1[h] += __shfl_xor_sync(~0u, p1[h], o);
        }
    if ((lane & 3) == 0) {
        #pragma unroll
        for (int h = 0; h < NH; h++) {
            S[(O_SPC >> 2) + (r0 * 8 + h) * 2 + cg] = p0[h];
            S[(O_SPC >> 2) + (r1 * 8 + h) * 2 + cg] = p1[h];
        }
    }
    __syncthreads();

    for (int e = t; e < NH * 128; e += 512) {
        int h = e >> 7, rr = e & 127;
        float sc = (S[(O_SPC >> 2) + (rr * 8 + h) * 2] + S[(O_SPC >> 2) + (rr * 8 + h) * 2 + 1]
                    + S[(O_QB >> 2) + h]) * S[(O_IOR >> 2) + e];
        S[(O_WSM >> 2) + e] = sc;
    }
    __syncthreads();
    if (wid < NH) {
        float v0 = S[(O_WSM >> 2) + wid * 128 + lane];
        float v1 = S[(O_WSM >> 2) + wid * 128 + 32 + lane];
        float v2 = S[(O_WSM >> 2) + wid * 128 + 64 + lane];
        float v3 = S[(O_WSM >> 2) + wid * 128 + 96 + lane];
        float mx = fmaxf(fmaxf(v0, v1), fmaxf(v2, v3));
        #pragma unroll
        for (int o = 16; o >= 1; o >>= 1) mx = fmaxf(mx, __shfl_xor_sync(~0u, mx, o));
        float e0 = __expf(v0 - mx), e1 = __expf(v1 - mx);
        float e2 = __expf(v2 - mx), e3 = __expf(v3 - mx);
        S[(O_WSM >> 2) + wid * 128 + lane] = e0;
        S[(O_WSM >> 2) + wid * 128 + 32 + lane] = e1;
        S[(O_WSM >> 2) + wid * 128 + 64 + lane] = e2;
        S[(O_WSM >> 2) + wid * 128 + 96 + lane] = e3;
        float es = (e0 + e1) + (e2 + e3);
        #pragma unroll
        for (int o = 16; o >= 1; o >>= 1) es += __shfl_xor_sync(~0u, es, o);
        if (lane == 0) { g_pmax[j * NH + wid] = mx; g_psum[j * NH + wid] = es; }
    }
    __syncthreads();

    // ctx: sliced rows, per-thread 8-head float4 accum
    {
        const int c4 = t & 63, sl = t >> 6;
        float4 a8[NH];
        #pragma unroll
        for (int h = 0; h < NH; h++) a8[h] = make_float4(0.f, 0.f, 0.f, 0.f);
        for (int r = sl * 16; r < sl * 16 + 16; r++) {
            float4 mv = *(float4*)&S[(O_MSM >> 2) + r * 260 + c4 * 4];
            #pragma unroll
            for (int h = 0; h < NH; h++) {
                float w = S[(O_WSM >> 2) + h * 128 + r];
                a8[h].x += w * mv.x; a8[h].y += w * mv.y;
                a8[h].z += w * mv.z; a8[h].w += w * mv.w;
            }
        }
        #pragma unroll
        for (int h = 0; h < NH; h++)
            *(float4*)&S[(O_SPC >> 2) + ((sl * 8 + h) * 64 + c4) * 4] = a8[h];
        __syncthreads();
        const int hh = t >> 6, cc = t & 63;
        float4 s4 = make_float4(0.f, 0.f, 0.f, 0.f);
        #pragma unroll
        for (int s2 = 0; s2 < 8; s2++) {
            float4 v = *(float4*)&S[(O_SPC >> 2) + ((s2 * 8 + hh) * 64 + cc) * 4];
            s4.x += v.x; s4.y += v.y; s4.z += v.z; s4.w += v.w;
        }
        ((float4*)g_pctx)[(size_t)j * 512 + hh * 64 + cc] = s4;
    }
}

// ---- K2: combine partials + V-proj + residual + LN + FFN ----
__global__ void k2(const float* __restrict__ query, const float* __restrict__ W_kv,
                   const float* __restrict__ b_kv, const float* __restrict__ g_f,
                   const float* __restrict__ be_f, const float* __restrict__ W1,
                   const float* __restrict__ b1, const float* __restrict__ W2,
                   const float* __restrict__ b2, float* __restrict__ out) {
    __shared__ float pm[128 * NH], ps[128 * NH], gm[NH], gs[NH];
    __shared__ float ctxn[NH * C_], xs[C_], hs[C_], us[FFN], red[8], red2[8];
    const int b = blockIdx.x, t = threadIdx.x;
    for (int i = t; i < 128 * NH; i += 256) {
        pm[i] = g_pmax[b * 128 * NH + i];
        ps[i] = g_psum[b * 128 * NH + i];
    }
    __syncthreads();
    {
        const int w = t >> 5, lane = t & 31;
        float m0 = pm[lane * NH + w], m1 = pm[(lane + 32) * NH + w];
        float m2 = pm[(lane + 64) * NH + w], m3 = pm[(lane + 96) * NH + w];
        float mx = fmaxf(fmaxf(m0, m1), fmaxf(m2, m3));
        #pragma unroll
        for (int o = 16; o >= 1; o >>= 1) mx = fmaxf(mx, __shfl_xor_sync(~0u, mx, o));
        float sm = ps[lane * NH + w] * __expf(m0 - mx) + ps[(lane + 32) * NH + w] * __expf(m1 - mx)
                 + ps[(lane + 64) * NH + w] * __expf(m2 - mx) + ps[(lane + 96) * NH + w] * __expf(m3 - mx);
        #pragma unroll
        for (int o = 16; o >= 1; o >>= 1) sm += __shfl_xor_sync(~0u, sm, o);
        if (lane == 0) { gm[w] = mx; gs[w] = sm; }
    }
    __syncthreads();
    {
        const int h = t >> 5, c0 = (t & 31) * 8;
        float a[8];
        #pragma unroll
        for (int q = 0; q < 8; q++) a[q] = 0.f;
        for (int ch = 0; ch < 128; ch++) {
            float f = __expf(pm[ch * NH + h] - gm[h]);
            const float4* p = (const float4*)&g_pctx[((size_t)(b * 128 + ch) * NH + h) * C_ + c0];
            float4 v0 = p[0], v1 = p[1];
            a[0] += f * v0.x; a[1] += f * v0.y; a[2] += f * v0.z; a[3] += f * v0.w;
            a[4] += f * v1.x; a[5] += f * v1.y; a[6] += f * v1.z; a[7] += f * v1.w;
        }
        float inv = 1.f / gs[h];
        #pragma unroll
        for (int q = 0; q < 8; q++) ctxn[h * C_ + c0 + q] = a[q] * inv;
    }
    __syncthreads();
    {
        const int h = t >> 5;
        float a0 = 0.f, a1 = 0.f, a2 = 0.f, a3 = 0.f;
        #pragma unroll 8
        for (int c = 0; c < C_; c += 4) {
            a0 += ctxn[h * C_ + c] * W_kv[c * (2 * C_) + C_ + t];
            a1 += ctxn[h * C_ + c + 1] * W_kv[(c + 1) * (2 * C_) + C_ + t];
            a2 += ctxn[h * C_ + c + 2] * W_kv[(c + 2) * (2 * C_) + C_ + t];
            a3 += ctxn[h * C_ + c + 3] * W_kv[(c + 3) * (2 * C_) + C_ + t];
        }
        float x = b_kv[C_ + t] + (a0 + a1) + (a2 + a3) + query[b * C_ + t];
        xs[t] = x;
        float s = x, s2 = x * x;
        #pragma unroll
        for (int o = 16; o >= 1; o >>= 1) {
            s += __shfl_xor_sync(~0u, s, o);
            s2 += __shfl_xor_sync(~0u, s2, o);
        }
        if ((t & 31) == 0) { red[t >> 5] = s; red2[t >> 5] = s2; }
        __syncthreads();
        float su = 0.f, sq = 0.f;
        #pragma unroll
        for (int i = 0; i < 8; i++) { su += red[i]; sq += red2[i]; }
        float mean = su / C_, var = sq / C_ - mean * mean, rs = rsqrtf(var + EPS);
        hs[t] = (x - mean) * rs * g_f[t] + be_f[t];
    }
    __syncthreads();
    for (int f = t; f < FFN; f += 256) {
        float a0 = 0.f, a1 = 0.f, a2 = 0.f, a3 = 0.f;
        #pragma unroll 8
        for (int c = 0; c < C_; c += 4) {
            a0 += hs[c] * W1[c * FFN + f];
            a1 += hs[c + 1] * W1[(c + 1) * FFN + f];
            a2 += hs[c + 2] * W1[(c + 2) * FFN + f];
            a3 += hs[c + 3] * W1[(c + 3) * FFN + f];
        }
        float u = b1[f] + (a0 + a1) + (a2 + a3);
        us[f] = 0.5f * u * (1.f + erff(u * 0.70710678118654752f));
    }
    __syncthreads();
    {
        float a0 = 0.f, a1 = 0.f, a2 = 0.f, a3 = 0.f;
        #pragma unroll 8
        for (int f = 0; f < FFN; f += 4) {
            a0 += us[f] * W2[f * C_ + t];
            a1 += us[f + 1] * W2[(f + 1) * C_ + t];
            a2 += us[f + 2] * W2[(f + 2) * C_ + t];
            a3 += us[f + 3] * W2[(f + 3) * C_ + t];
        }
        out[b * C_ + t] = xs[t] + b2[t] + (a0 + a1) + (a2 + a3);
    }
}

extern "C" void kernel_launch(void* const* d_in, const int* in_sizes, int n_in,
                              void* d_out, int out_size) {
    const float* query = (const float*)d_in[0];
    const float* mem   = (const float*)d_in[1];
    const float* ior   = (const float*)d_in[2];
    const float* W_ip  = (const float*)d_in[3];
    const float* b_ip  = (const float*)d_in[4];
    const float* g_ip  = (const float*)d_in[5];
    const float* be_ip = (const float*)d_in[6];
    const float* W_q   = (const float*)d_in[7];
    const float* b_q   = (const float*)d_in[8];
    const float* W_kv  = (const float*)d_in[9];
    const float* b_kv  = (const float*)d_in[10];
    const float* g_q   = (const float*)d_in[11];
    const float* be_q  = (const float*)d_in[12];
    const float* g_f   = (const float*)d_in[13];
    const float* be_f  = (const float*)d_in[14];
    const float* W1    = (const float*)d_in[15];
    const float* b1    = (const float*)d_in[16];
    const float* W2    = (const float*)d_in[17];
    const float* b2    = (const float*)d_in[18];

    cudaFuncSetAttribute(k1, cudaFuncAttributeMaxDynamicSharedMemorySize, SM1);
    k0b<<<C_, C_>>>(W_ip);
    k0<<<B_, C_>>>(query, W_q, b_q, W_kv, b_kv, g_q, be_q);
    k1<<<JOBS, 512, SM1>>>(mem, ior, b_ip, g_ip, be_ip);
    k2<<<B_, C_>>>(query, W_kv, b_kv, g_f, be_f, W1, b1, W2, b2, (float*)d_out);
}

// round 6
// speedup vs baseline: 2.3794x; 1.3689x over previous
#include <cuda_runtime.h>
#include <cuda_fp16.h>
#include <cstdint>
#include <cstddef>

#define B_ 16
#define L_ 16384
#define C_ 256
#define NH 8
#define FFN 512
#define EPS 1e-5f
#define SCALE_ATT 0.17677669529663687f
#define JOBS 2048

// k1 smem byte offsets
#define O_A   0         /* A fp16: 128 x 40 halves = 10240 */
#define O_B0  10240     /* B fp16 double buffer: 2 x 20480 */
#define O_MSM 0         /* m fp16 [128][264], overlays GEMM bufs, 67584 B */
#define O_SPC 67584     /* 65536: score partials then ctx partials */
#define O_QKP 133120    /* 4 replicas x 2116 floats = 33856 */
#define O_IOR 166976
#define O_WSM 171072
#define O_ST  175168
#define O_QB  177216
#define O_BIP 177248
#define O_GIP 178272
#define O_BEI 179296
#define SM1   180320

__device__ float g_qkp[B_ * NH * C_];
__device__ float g_qb[B_ * NH];
__device__ float g_pmax[JOBS * NH];
__device__ float g_psum[JOBS * NH];
__device__ float g_pctx[(size_t)JOBS * NH * C_];
__device__ float g_ctxn[B_ * NH * C_];
__device__ __align__(16) __half g_wh[C_ * C_];   // W_ip^T fp16, n-major

__device__ __forceinline__ uint32_t smem_u32(const void* p) {
    uint32_t a;
    asm("{ .reg .u64 t; cvta.to.shared.u64 t, %1; cvt.u32.u64 %0, t; }" : "=r"(a) : "l"(p));
    return a;
}
__device__ __forceinline__ void ldmx4(uint32_t* r, uint32_t a) {
    asm volatile("ldmatrix.sync.aligned.m8n8.x4.shared.b16 {%0,%1,%2,%3}, [%4];"
        : "=r"(r[0]), "=r"(r[1]), "=r"(r[2]), "=r"(r[3]) : "r"(a));
}
__device__ __forceinline__ void mma16816(float* d, const uint32_t* a, uint32_t b0, uint32_t b1) {
    asm volatile("mma.sync.aligned.m16n8k16.row.col.f32.f16.f16.f32 "
        "{%0,%1,%2,%3}, {%4,%5,%6,%7}, {%8,%9}, {%0,%1,%2,%3};"
        : "+f"(d[0]), "+f"(d[1]), "+f"(d[2]), "+f"(d[3])
        : "r"(a[0]), "r"(a[1]), "r"(a[2]), "r"(a[3]), "r"(b0), "r"(b1));
}
#define CPA(dst, src) asm volatile("cp.async.cg.shared.global [%0], [%1], 16;" :: "r"(dst), "l"(src))
#define CPC() asm volatile("cp.async.commit_group;" ::: "memory")
#define CPW(n) asm volatile("cp.async.wait_group %0;" :: "n"(n) : "memory")

// ---- K0b: W_ip^T -> fp16, n-major ----
__global__ void k0b(const float* __restrict__ W_ip) {
    const int n = blockIdx.x, k = threadIdx.x;
    g_wh[n * C_ + k] = __float2half_rn(W_ip[k * C_ + n]);
}

// ---- K0: fold LN(query)@W_q into qkp/qb ----
__global__ void k0(const float* __restrict__ query, const float* __restrict__ W_q,
                   const float* __restrict__ b_q, const float* __restrict__ W_kv,
                   const float* __restrict__ b_kv, const float* __restrict__ g_q,
                   const float* __restrict__ be_q) {
    __shared__ float qn[C_], qs[C_], red[8], red2[8];
    const int b = blockIdx.x, t = threadIdx.x;
    float x = query[b * C_ + t];
    float s = x, s2 = x * x;
    #pragma unroll
    for (int o = 16; o >= 1; o >>= 1) {
        s += __shfl_xor_sync(~0u, s, o);
        s2 += __shfl_xor_sync(~0u, s2, o);
    }
    if ((t & 31) == 0) { red[t >> 5] = s; red2[t >> 5] = s2; }
    __syncthreads();
    float su = 0.f, sq = 0.f;
    #pragma unroll
    for (int i = 0; i < 8; i++) { su += red[i]; sq += red2[i]; }
    float mean = su / C_, var = sq / C_ - mean * mean, rs = rsqrtf(var + EPS);
    qn[t] = (x - mean) * rs * g_q[t] + be_q[t];
    __syncthreads();
    float a0 = 0.f, a1 = 0.f, a2 = 0.f, a3 = 0.f;
    #pragma unroll 8
    for (int c = 0; c < C_; c += 4) {
        a0 += qn[c] * W_q[c * C_ + t];
        a1 += qn[c + 1] * W_q[(c + 1) * C_ + t];
        a2 += qn[c + 2] * W_q[(c + 2) * C_ + t];
        a3 += qn[c + 3] * W_q[(c + 3) * C_ + t];
    }
    qs[t] = b_q[t] + (a0 + a1) + (a2 + a3);
    __syncthreads();
    const float* wr = W_kv + (size_t)t * (2 * C_);
    #pragma unroll
    for (int h = 0; h < NH; h++) {
        float acc = 0.f;
        #pragma unroll 8
        for (int d = 0; d < 32; d++) acc += qs[h * 32 + d] * wr[h * 32 + d];
        g_qkp[(b * NH + h) * C_ + t] = acc * SCALE_ATT;
    }
    if (t < NH) {
        float qb = 0.f;
        #pragma unroll 8
        for (int d = 0; d < 32; d++) qb += qs[t * 32 + d] * b_kv[t * 32 + d];
        g_qb[b * NH + t] = qb * SCALE_ATT;
    }
}

// ---- K1: fp16 HMMA fused main kernel (one 128-row tile per block) ----
__global__ void __launch_bounds__(512, 1)
k1(const float* __restrict__ mem, const float* __restrict__ ior,
   const float* __restrict__ b_ip, const float* __restrict__ g_ip,
   const float* __restrict__ be_ip) {
    extern __shared__ char sm[];
    float* S = (float*)sm;
    const uint32_t smb = smem_u32(sm);
    const int t = threadIdx.x, lane = t & 31, wid = t >> 5;
    const int rg = wid >> 1, cg = wid & 1;
    const int j = blockIdx.x, b = j >> 7, row0 = (j & 127) << 7;

    // per-block init
    for (int i = t; i < NH * C_; i += 512) {
        float v = g_qkp[b * NH * C_ + i];
        int h = i >> 8, c = i & 255;
        #pragma unroll
        for (int q = 0; q < 4; q++)
            S[(O_QKP >> 2) + q * 2116 + h * 264 + c] = v;
    }
    if (t < NH) S[(O_QB >> 2) + t] = g_qb[b * NH + t];
    for (int i = t; i < NH * 128; i += 512)
        S[(O_IOR >> 2) + i] = ior[(size_t)(b * NH + (i >> 7)) * L_ + row0 + (i & 127)];
    if (t < C_) {
        S[(O_BIP >> 2) + t] = b_ip[t];
        S[(O_GIP >> 2) + t] = g_ip[t];
        S[(O_BEI >> 2) + t] = be_ip[t];
    }

    // ---- GEMM: [128,256] = A[128,256] @ B^T, fp16, K-chunks of 32 ----
    const float4* mem4 = (const float4*)mem;
    const int ar = t >> 2, aq = t & 3;
    const size_t abase = (size_t)(b * L_ + row0 + ar) * 64;
    float4 av0 = mem4[abase + aq * 2], av1 = mem4[abase + aq * 2 + 1];

    const int bn = t >> 1, bf = t & 1;
    {
        const char* sH = (const char*)g_wh + ((size_t)bn * 256 + bf * 16) * 2;
        uint32_t d0 = smb + O_B0 + bn * 80 + bf * 32;
        CPA(d0, sH); CPA(d0 + 16, sH + 16);
        CPC();
    }

    float d[16][4];
    #pragma unroll
    for (int i = 0; i < 16; i++)
        #pragma unroll
        for (int q = 0; q < 4; q++) d[i][q] = 0.f;

    const int lg = lane >> 3, lr = lane & 7;
    const uint32_t aAddr = smb + O_A + (rg * 16 + ((lg & 1) << 3) + lr) * 80 + (lg >> 1) * 16;
    const uint32_t bOff = (cg * 128 + ((lg >> 1) << 3) + lr) * 80 + (lg & 1) * 16;

    for (int kc = 0; kc < 8; kc++) {
        __syncthreads();
        {   // A regs -> smem fp16
            __half2 h0 = __floats2half2_rn(av0.x, av0.y);
            __half2 h1 = __floats2half2_rn(av0.z, av0.w);
            __half2 h2 = __floats2half2_rn(av1.x, av1.y);
            __half2 h3 = __floats2half2_rn(av1.z, av1.w);
            *(uint4*)(sm + O_A + ar * 80 + aq * 16) =
                make_uint4(*(uint32_t*)&h0, *(uint32_t*)&h1, *(uint32_t*)&h2, *(uint32_t*)&h3);
        }
        if (kc < 7) {
            av0 = mem4[abase + (kc + 1) * 8 + aq * 2];
            av1 = mem4[abase + (kc + 1) * 8 + aq * 2 + 1];
            const char* sH = (const char*)g_wh + ((size_t)bn * 256 + (kc + 1) * 32 + bf * 16) * 2;
            uint32_t d0 = smb + O_B0 + ((kc + 1) & 1) * 20480 + bn * 80 + bf * 32;
            CPA(d0, sH); CPA(d0 + 16, sH + 16);
            CPC();
            CPW(1);
        } else {
            CPW(0);
        }
        __syncthreads();

        uint32_t bufB = smb + O_B0 + (kc & 1) * 20480 + bOff;
        #pragma unroll
        for (int ks = 0; ks < 2; ks++) {
            uint32_t ah[4];
            ldmx4(ah, aAddr + ks * 32);
            #pragma unroll
            for (int jt = 0; jt < 8; jt++) {
                uint32_t bh[4];
                ldmx4(bh, bufB + jt * 1280 + ks * 32);
                mma16816(d[2 * jt], ah, bh[0], bh[1]);
                mma16816(d[2 * jt + 1], ah, bh[2], bh[3]);
            }
        }
    }
    __syncthreads();   // ldmatrix reads done; msm may overwrite GEMM bufs

    // ---- epilogue ----
    const int r0 = rg * 16 + (lane >> 2), r1 = r0 + 8;
    const int cq = (lane & 3) * 2;

    float s0 = 0.f, q0 = 0.f, s1 = 0.f, q1 = 0.f;
    #pragma unroll
    for (int nt = 0; nt < 16; nt++) {
        int c = cg * 128 + nt * 8 + cq;
        float2 bb = *(float2*)&S[(O_BIP >> 2) + c];
        float x0 = fmaxf(d[nt][0] + bb.x, 0.f), x1 = fmaxf(d[nt][1] + bb.y, 0.f);
        float y0 = fmaxf(d[nt][2] + bb.x, 0.f), y1 = fmaxf(d[nt][3] + bb.y, 0.f);
        d[nt][0] = x0; d[nt][1] = x1; d[nt][2] = y0; d[nt][3] = y1;
        s0 += x0 + x1; q0 += x0 * x0 + x1 * x1;
        s1 += y0 + y1; q1 += y0 * y0 + y1 * y1;
    }
    #pragma unroll
    for (int o = 1; o <= 2; o <<= 1) {
        s0 += __shfl_xor_sync(~0u, s0, o); q0 += __shfl_xor_sync(~0u, q0, o);
        s1 += __shfl_xor_sync(~0u, s1, o); q1 += __shfl_xor_sync(~0u, q1, o);
    }
    if ((lane & 3) == 0) {
        S[(O_ST >> 2) + r0 * 2 + cg] = s0; S[(O_ST >> 2) + 256 + r0 * 2 + cg] = q0;
        S[(O_ST >> 2) + r1 * 2 + cg] = s1; S[(O_ST >> 2) + 256 + r1 * 2 + cg] = q1;
    }
    __syncthreads();
    float mean0, rs0, mean1, rs1;
    {
        float su = S[(O_ST >> 2) + r0 * 2] + S[(O_ST >> 2) + r0 * 2 + 1];
        float sq = S[(O_ST >> 2) + 256 + r0 * 2] + S[(O_ST >> 2) + 256 + r0 * 2 + 1];
        mean0 = su / C_; rs0 = rsqrtf(sq / C_ - mean0 * mean0 + EPS);
        su = S[(O_ST >> 2) + r1 * 2] + S[(O_ST >> 2) + r1 * 2 + 1];
        sq = S[(O_ST >> 2) + 256 + r1 * 2] + S[(O_ST >> 2) + 256 + r1 * 2 + 1];
        mean1 = su / C_; rs1 = rsqrtf(sq / C_ - mean1 * mean1 + EPS);
    }

    float p0[NH], p1[NH];
    #pragma unroll
    for (int h = 0; h < NH; h++) { p0[h] = 0.f; p1[h] = 0.f; }
    const int qrep = (O_QKP >> 2) + (lane & 3) * 2116;
    #pragma unroll
    for (int nt = 0; nt < 16; nt++) {
        int c = cg * 128 + nt * 8 + cq;
        float2 gg = *(float2*)&S[(O_GIP >> 2) + c];
        float2 ee = *(float2*)&S[(O_BEI >> 2) + c];
        float v00 = (d[nt][0] - mean0) * rs0 * gg.x + ee.x;
        float v01 = (d[nt][1] - mean0) * rs0 * gg.y + ee.y;
        float v10 = (d[nt][2] - mean1) * rs1 * gg.x + ee.x;
        float v11 = (d[nt][3] - mean1) * rs1 * gg.y + ee.y;
        *(__half2*)(sm + O_MSM + (r0 * 264 + c) * 2) = __floats2half2_rn(v00, v01);
        *(__half2*)(sm + O_MSM + (r1 * 264 + c) * 2) = __floats2half2_rn(v10, v11);
        #pragma unroll
        for (int h = 0; h < NH; h++) {
            float2 qv = *(float2*)&S[qrep + h * 264 + c];
            p0[h] += v00 * qv.x + v01 * qv.y;
            p1[h] += v10 * qv.x + v11 * qv.y;
        }
    }
    #pragma unroll
    for (int o = 1; o <= 2; o <<= 1)
        #pragma unroll
        for (int h = 0; h < NH; h++) {
            p0[h] += __shfl_xor_sync(~0u, p0[h], o);
            p1[h] += __shfl_xor_sync(~0u, p1[h], o);
        }
    if ((lane & 3) == 0) {
        #pragma unroll
        for (int h = 0; h < NH; h++) {
            S[(O_SPC >> 2) + (r0 * 8 + h) * 2 + cg] = p0[h];
            S[(O_SPC >> 2) + (r1 * 8 + h) * 2 + cg] = p1[h];
        }
    }
    __syncthreads();

    for (int e = t; e < NH * 128; e += 512) {
        int h = e >> 7, rr = e & 127;
        S[(O_WSM >> 2) + e] = (S[(O_SPC >> 2) + (rr * 8 + h) * 2]
                               + S[(O_SPC >> 2) + (rr * 8 + h) * 2 + 1]
                               + S[(O_QB >> 2) + h]) * S[(O_IOR >> 2) + e];
    }
    __syncthreads();
    if (wid < NH) {
        float v0 = S[(O_WSM >> 2) + wid * 128 + lane];
        float v1 = S[(O_WSM >> 2) + wid * 128 + 32 + lane];
        float v2 = S[(O_WSM >> 2) + wid * 128 + 64 + lane];
        float v3 = S[(O_WSM >> 2) + wid * 128 + 96 + lane];
        float mx = fmaxf(fmaxf(v0, v1), fmaxf(v2, v3));
        #pragma unroll
        for (int o = 16; o >= 1; o >>= 1) mx = fmaxf(mx, __shfl_xor_sync(~0u, mx, o));
        float e0 = __expf(v0 - mx), e1 = __expf(v1 - mx);
        float e2 = __expf(v2 - mx), e3 = __expf(v3 - mx);
        S[(O_WSM >> 2) + wid * 128 + lane] = e0;
        S[(O_WSM >> 2) + wid * 128 + 32 + lane] = e1;
        S[(O_WSM >> 2) + wid * 128 + 64 + lane] = e2;
        S[(O_WSM >> 2) + wid * 128 + 96 + lane] = e3;
        float es = (e0 + e1) + (e2 + e3);
        #pragma unroll
        for (int o = 16; o >= 1; o >>= 1) es += __shfl_xor_sync(~0u, es, o);
        if (lane == 0) { g_pmax[j * NH + wid] = mx; g_psum[j * NH + wid] = es; }
    }
    __syncthreads();

    // ctx partial: sliced rows, per-thread 8-head float4 accum
    {
        const int c4 = t & 63, sl = t >> 6;
        float4 a8[NH];
        #pragma unroll
        for (int h = 0; h < NH; h++) a8[h] = make_float4(0.f, 0.f, 0.f, 0.f);
        for (int r = sl * 16; r < sl * 16 + 16; r++) {
            uint2 u = *(uint2*)(sm + O_MSM + (r * 264 + c4 * 4) * 2);
            float2 f01 = __half22float2(*(__half2*)&u.x);
            float2 f23 = __half22float2(*(__half2*)&u.y);
            #pragma unroll
            for (int h = 0; h < NH; h++) {
                float w = S[(O_WSM >> 2) + h * 128 + r];
                a8[h].x += w * f01.x; a8[h].y += w * f01.y;
                a8[h].z += w * f23.x; a8[h].w += w * f23.y;
            }
        }
        #pragma unroll
        for (int h = 0; h < NH; h++)
            *(float4*)&S[(O_SPC >> 2) + ((sl * 8 + h) * 64 + c4) * 4] = a8[h];
        __syncthreads();
        const int hh = t >> 6, cc = t & 63;
        float4 s4 = make_float4(0.f, 0.f, 0.f, 0.f);
        #pragma unroll
        for (int s2 = 0; s2 < 8; s2++) {
            float4 v = *(float4*)&S[(O_SPC >> 2) + ((s2 * 8 + hh) * 64 + cc) * 4];
            s4.x += v.x; s4.y += v.y; s4.z += v.z; s4.w += v.w;
        }
        ((float4*)g_pctx)[(size_t)j * 512 + hh * 64 + cc] = s4;
    }
}

// ---- K2a: parallel softmax-combine of 128 partials, one block per (b,h) ----
__global__ void k2a() {
    __shared__ float pm[128], ps[128], ef[128], red[4], red2[4];
    const int b = blockIdx.x >> 3, h = blockIdx.x & 7;
    const int t = threadIdx.x, lane = t & 31;
    if (t < 128) {
        pm[t] = g_pmax[(b * 128 + t) * NH + h];
        ps[t] = g_psum[(b * 128 + t) * NH + h];
    }
    __syncthreads();
    if (t < 128) {
        float v = pm[t];
        #pragma unroll
        for (int o = 16; o >= 1; o >>= 1) v = fmaxf(v, __shfl_xor_sync(~0u, v, o));
        if (lane == 0) red[t >> 5] = v;
    }
    __syncthreads();
    float gmax = fmaxf(fmaxf(red[0], red[1]), fmaxf(red[2], red[3]));
    if (t < 128) ef[t] = __expf(pm[t] - gmax);
    __syncthreads();
    if (t < 128) {
        float v = ps[t] * ef[t];
        #pragma unroll
        for (int o = 16; o >= 1; o >>= 1) v += __shfl_xor_sync(~0u, v, o);
        if (lane == 0) red2[t >> 5] = v;
    }
    __syncthreads();
    float inv = 1.f / (red2[0] + red2[1] + red2[2] + red2[3]);
    float acc = 0.f;
    const float* p = g_pctx + ((size_t)(b * 128) * NH + h) * C_ + t;
    #pragma unroll 4
    for (int ch = 0; ch < 128; ch++)
        acc += ef[ch] * p[(size_t)ch * NH * C_];
    g_ctxn[(b * NH + h) * C_ + t] = acc * inv;
}

// ---- K2b: V-proj + residual + LN + FFN ----
__global__ void k2b(const float* __restrict__ query, const float* __restrict__ W_kv,
                    const float* __restrict__ b_kv, const float* __restrict__ g_f,
                    const float* __restrict__ be_f, const float* __restrict__ W1,
                    const float* __restrict__ b1, const float* __restrict__ W2,
                    const float* __restrict__ b2, float* __restrict__ out) {
    __shared__ float ctxn[NH * C_], xs[C_], hs[C_], us[FFN], red[8], red2[8];
    const int b = blockIdx.x, t = threadIdx.x;
    for (int i = t; i < NH * C_; i += 256) ctxn[i] = g_ctxn[b * NH * C_ + i];
    __syncthreads();
    {
        const int h = t >> 5;
        float a0 = 0.f, a1 = 0.f, a2 = 0.f, a3 = 0.f;
        #pragma unroll 8
        for (int c = 0; c < C_; c += 4) {
            a0 += ctxn[h * C_ + c] * W_kv[c * (2 * C_) + C_ + t];
            a1 += ctxn[h * C_ + c + 1] * W_kv[(c + 1) * (2 * C_) + C_ + t];
            a2 += ctxn[h * C_ + c + 2] * W_kv[(c + 2) * (2 * C_) + C_ + t];
            a3 += ctxn[h * C_ + c + 3] * W_kv[(c + 3) * (2 * C_) + C_ + t];
        }
        float x = b_kv[C_ + t] + (a0 + a1) + (a2 + a3) + query[b * C_ + t];
        xs[t] = x;
        float s = x, s2 = x * x;
        #pragma unroll
        for (int o = 16; o >= 1; o >>= 1) {
            s += __shfl_xor_sync(~0u, s, o);
            s2 += __shfl_xor_sync(~0u, s2, o);
        }
        if ((t & 31) == 0) { red[t >> 5] = s; red2[t >> 5] = s2; }
        __syncthreads();
        float su = 0.f, sq = 0.f;
        #pragma unroll
        for (int i = 0; i < 8; i++) { su += red[i]; sq += red2[i]; }
        float mean = su / C_, var = sq / C_ - mean * mean, rs = rsqrtf(var + EPS);
        hs[t] = (x - mean) * rs * g_f[t] + be_f[t];
    }
    __syncthreads();
    for (int f = t; f < FFN; f += 256) {
        float a0 = 0.f, a1 = 0.f, a2 = 0.f, a3 = 0.f;
        #pragma unroll 8
        for (int c = 0; c < C_; c += 4) {
            a0 += hs[c] * W1[c * FFN + f];
            a1 += hs[c + 1] * W1[(c + 1) * FFN + f];
            a2 += hs[c + 2] * W1[(c + 2) * FFN + f];
            a3 += hs[c + 3] * W1[(c + 3) * FFN + f];
        }
        float u = b1[f] + (a0 + a1) + (a2 + a3);
        us[f] = 0.5f * u * (1.f + erff(u * 0.70710678118654752f));
    }
    __syncthreads();
    {
        float a0 = 0.f, a1 = 0.f, a2 = 0.f, a3 = 0.f;
        #pragma unroll 8
        for (int f = 0; f < FFN; f += 4) {
            a0 += us[f] * W2[f * C_ + t];
            a1 += us[f + 1] * W2[(f + 1) * C_ + t];
            a2 += us[f + 2] * W2[(f + 2) * C_ + t];
            a3 += us[f + 3] * W2[(f + 3) * C_ + t];
        }
        out[b * C_ + t] = xs[t] + b2[t] + (a0 + a1) + (a2 + a3);
    }
}

extern "C" void kernel_launch(void* const* d_in, const int* in_sizes, int n_in,
                              void* d_out, int out_size) {
    const float* query = (const float*)d_in[0];
    const float* mem   = (const float*)d_in[1];
    const float* ior   = (const float*)d_in[2];
    const float* W_ip  = (const float*)d_in[3];
    const float* b_ip  = (const float*)d_in[4];
    const float* g_ip  = (const float*)d_in[5];
    const float* be_ip = (const float*)d_in[6];
    const float* W_q   = (const float*)d_in[7];
    const float* b_q   = (const float*)d_in[8];
    const float* W_kv  = (const float*)d_in[9];
    const float* b_kv  = (const float*)d_in[10];
    const float* g_q   = (const float*)d_in[11];
    const float* be_q  = (const float*)d_in[12];
    const float* g_f   = (const float*)d_in[13];
    const float* be_f  = (const float*)d_in[14];
    const float* W1    = (const float*)d_in[15];
    const float* b1    = (const float*)d_in[16];
    const float* W2    = (const float*)d_in[17];
    const float* b2    = (const float*)d_in[18];

    cudaFuncSetAttribute(k1, cudaFuncAttributeMaxDynamicSharedMemorySize, SM1);
    k0b<<<C_, C_>>>(W_ip);
    k0<<<B_, C_>>>(query, W_q, b_q, W_kv, b_kv, g_q, be_q);
    k1<<<JOBS, 512, SM1>>>(mem, ior, b_ip, g_ip, be_ip);
    k2a<<<B_ * NH, 256>>>();
    k2b<<<B_, C_>>>(query, W_kv, b_kv, g_f, be_f, W1, b1, W2, b2, (float*)d_out);
}

// round 7
// speedup vs baseline: 2.4109x; 1.0132x over previous
#include <cuda_runtime.h>
#include <cuda_fp16.h>
#include <cstdint>
#include <cstddef>

#define B_ 16
#define L_ 16384
#define C_ 256
#define NH 8
#define FFN 512
#define EPS 1e-5f
#define SCALE_ATT 0.17677669529663687f
#define JOBS 2048

// k1 smem byte offsets
#define O_A   0         /* A fp16: 128 x 40 halves = 10240 */
#define O_B0  10240     /* B fp16 double buffer: 2 x 20480 */
#define O_MSM 0         /* m^ fp16 [128][264], overlays GEMM bufs, 67584 B */
#define O_SPC 67584     /* score partials then ctx partials (64 KB) */
#define O_GQ  133120    /* gq fp32 [8][264] = 8448 B */
#define O_IOR 141632
#define O_WSM 145728
#define O_ST  149824    /* row sums / sumsq: 512 floats */
#define O_MU  151872
#define O_RS  152384
#define O_CG  152896    /* G[8] */
#define O_CQC 152928    /* QC[8] */
#define O_CS2 152960    /* S2[8] */
#define O_CW  152992    /* W[8] */
#define O_BIP 153024
#define O_GIP 154048
#define O_BEI 155072
#define SM1   156096

__device__ float g_gq[B_ * NH * C_];
__device__ float g_G[B_ * NH];
__device__ float g_qc[B_ * NH];
__device__ float g_pmax[JOBS * NH];
__device__ float g_psum[JOBS * NH];
__device__ float g_pctx[(size_t)JOBS * NH * C_];
__device__ float g_ctxn[B_ * NH * C_];
__device__ __align__(16) __half g_wh[C_ * C_];   // W_ip^T fp16, n-major

__device__ __forceinline__ uint32_t smem_u32(const void* p) {
    uint32_t a;
    asm("{ .reg .u64 t; cvta.to.shared.u64 t, %1; cvt.u32.u64 %0, t; }" : "=r"(a) : "l"(p));
    return a;
}
__device__ __forceinline__ void ldmx4(uint32_t* r, uint32_t a) {
    asm volatile("ldmatrix.sync.aligned.m8n8.x4.shared.b16 {%0,%1,%2,%3}, [%4];"
        : "=r"(r[0]), "=r"(r[1]), "=r"(r[2]), "=r"(r[3]) : "r"(a));
}
__device__ __forceinline__ void mma16816(float* d, const uint32_t* a, uint32_t b0, uint32_t b1) {
    asm volatile("mma.sync.aligned.m16n8k16.row.col.f32.f16.f16.f32 "
        "{%0,%1,%2,%3}, {%4,%5,%6,%7}, {%8,%9}, {%0,%1,%2,%3};"
        : "+f"(d[0]), "+f"(d[1]), "+f"(d[2]), "+f"(d[3])
        : "r"(a[0]), "r"(a[1]), "r"(a[2]), "r"(a[3]), "r"(b0), "r"(b1));
}
#define CPA(dst, src) asm volatile("cp.async.cg.shared.global [%0], [%1], 16;" :: "r"(dst), "l"(src))
#define CPC() asm volatile("cp.async.commit_group;" ::: "memory")
#define CPW(n) asm volatile("cp.async.wait_group %0;" :: "n"(n) : "memory")

// ---- K0b: W_ip^T -> fp16, n-major ----
__global__ void k0b(const float* __restrict__ W_ip) {
    const int n = blockIdx.x, k = threadIdx.x;
    g_wh[n * C_ + k] = __float2half_rn(W_ip[k * C_ + n]);
}

// ---- K0: fold LN(query)@W_q into gq/G/QC ----
__global__ void k0(const float* __restrict__ query, const float* __restrict__ W_q,
                   const float* __restrict__ b_q, const float* __restrict__ W_kv,
                   const float* __restrict__ b_kv, const float* __restrict__ g_q,
                   const float* __restrict__ be_q, const float* __restrict__ g_ip,
                   const float* __restrict__ be_ip) {
    __shared__ float qn[C_], qs[C_], red[8], red2[8], sG[NH], sQ[NH];
    const int b = blockIdx.x, t = threadIdx.x;
    float x = query[b * C_ + t];
    float s = x, s2 = x * x;
    #pragma unroll
    for (int o = 16; o >= 1; o >>= 1) {
        s += __shfl_xor_sync(~0u, s, o);
        s2 += __shfl_xor_sync(~0u, s2, o);
    }
    if ((t & 31) == 0) { red[t >> 5] = s; red2[t >> 5] = s2; }
    __syncthreads();
    float su = 0.f, sq = 0.f;
    #pragma unroll
    for (int i = 0; i < 8; i++) { su += red[i]; sq += red2[i]; }
    float mean = su / C_, var = sq / C_ - mean * mean, rs = rsqrtf(var + EPS);
    qn[t] = (x - mean) * rs * g_q[t] + be_q[t];
    __syncthreads();
    float a0 = 0.f, a1 = 0.f, a2 = 0.f, a3 = 0.f;
    #pragma unroll 8
    for (int c = 0; c < C_; c += 4) {
        a0 += qn[c] * W_q[c * C_ + t];
        a1 += qn[c + 1] * W_q[(c + 1) * C_ + t];
        a2 += qn[c + 2] * W_q[(c + 2) * C_ + t];
        a3 += qn[c + 3] * W_q[(c + 3) * C_ + t];
    }
    qs[t] = b_q[t] + (a0 + a1) + (a2 + a3);
    __syncthreads();
    const float* wr = W_kv + (size_t)t * (2 * C_);
    const float gI = g_ip[t], bE = be_ip[t];
    for (int h = 0; h < NH; h++) {
        float acc = 0.f;
        #pragma unroll 8
        for (int d = 0; d < 32; d++) acc += qs[h * 32 + d] * wr[h * 32 + d];
        acc *= SCALE_ATT;
        g_gq[(b * NH + h) * C_ + t] = acc * gI;
        float r1v = acc * gI, r2v = acc * bE;
        #pragma unroll
        for (int o = 16; o >= 1; o >>= 1) {
            r1v += __shfl_xor_sync(~0u, r1v, o);
            r2v += __shfl_xor_sync(~0u, r2v, o);
        }
        if ((t & 31) == 0) { red[t >> 5] = r1v; red2[t >> 5] = r2v; }
        __syncthreads();
        if (t == 0) {
            float gsum = 0.f, qsum = 0.f;
            #pragma unroll
            for (int i = 0; i < 8; i++) { gsum += red[i]; qsum += red2[i]; }
            sG[h] = gsum; sQ[h] = qsum;
        }
        __syncthreads();
    }
    if (t < NH) {
        float qb = 0.f;
        #pragma unroll 8
        for (int d = 0; d < 32; d++) qb += qs[t * 32 + d] * b_kv[t * 32 + d];
        g_G[b * NH + t] = sG[t];
        g_qc[b * NH + t] = sQ[t] + qb * SCALE_ATT;
    }
}

// ---- K1: fp16 HMMA fused main kernel (one 128-row tile per block) ----
__global__ void __launch_bounds__(512, 1)
k1(const float* __restrict__ mem, const float* __restrict__ ior,
   const float* __restrict__ b_ip, const float* __restrict__ g_ip,
   const float* __restrict__ be_ip) {
    extern __shared__ char sm[];
    float* S = (float*)sm;
    const uint32_t smb = smem_u32(sm);
    const int t = threadIdx.x, lane = t & 31, wid = t >> 5;
    const int rg = wid >> 1, cg = wid & 1;
    const int j = blockIdx.x, b = j >> 7, row0 = (j & 127) << 7;

    // per-block init
    for (int i = t; i < NH * C_; i += 512)
        S[(O_GQ >> 2) + (i >> 8) * 264 + (i & 255)] = g_gq[b * NH * C_ + i];
    if (t < NH) {
        S[(O_CG >> 2) + t] = g_G[b * NH + t];
        S[(O_CQC >> 2) + t] = g_qc[b * NH + t];
    }
    for (int i = t; i < NH * 128; i += 512)
        S[(O_IOR >> 2) + i] = ior[(size_t)(b * NH + (i >> 7)) * L_ + row0 + (i & 127)];
    if (t < C_) {
        S[(O_BIP >> 2) + t] = b_ip[t];
        S[(O_GIP >> 2) + t] = g_ip[t];
        S[(O_BEI >> 2) + t] = be_ip[t];
    }

    // ---- GEMM: [128,256] = A[128,256] @ B^T, fp16, K-chunks of 32 ----
    const float4* mem4 = (const float4*)mem;
    const int ar = t >> 2, aq = t & 3;
    const size_t abase = (size_t)(b * L_ + row0 + ar) * 64;
    float4 av0 = mem4[abase + aq * 2], av1 = mem4[abase + aq * 2 + 1];

    const int bn = t >> 1, bf = t & 1;
    {
        const char* sH = (const char*)g_wh + ((size_t)bn * 256 + bf * 16) * 2;
        uint32_t d0 = smb + O_B0 + bn * 80 + bf * 32;
        CPA(d0, sH); CPA(d0 + 16, sH + 16);
        CPC();
    }

    float d[16][4];
    #pragma unroll
    for (int i = 0; i < 16; i++)
        #pragma unroll
        for (int q = 0; q < 4; q++) d[i][q] = 0.f;

    const int lg = lane >> 3, lr = lane & 7;
    const uint32_t aAddr = smb + O_A + (rg * 16 + ((lg & 1) << 3) + lr) * 80 + (lg >> 1) * 16;
    const uint32_t bOff = (cg * 128 + ((lg >> 1) << 3) + lr) * 80 + (lg & 1) * 16;

    for (int kc = 0; kc < 8; kc++) {
        __syncthreads();
        {
            __half2 h0 = __floats2half2_rn(av0.x, av0.y);
            __half2 h1 = __floats2half2_rn(av0.z, av0.w);
            __half2 h2 = __floats2half2_rn(av1.x, av1.y);
            __half2 h3 = __floats2half2_rn(av1.z, av1.w);
            *(uint4*)(sm + O_A + ar * 80 + aq * 16) =
                make_uint4(*(uint32_t*)&h0, *(uint32_t*)&h1, *(uint32_t*)&h2, *(uint32_t*)&h3);
        }
        if (kc < 7) {
            av0 = mem4[abase + (kc + 1) * 8 + aq * 2];
            av1 = mem4[abase + (kc + 1) * 8 + aq * 2 + 1];
            const char* sH = (const char*)g_wh + ((size_t)bn * 256 + (kc + 1) * 32 + bf * 16) * 2;
            uint32_t d0 = smb + O_B0 + ((kc + 1) & 1) * 20480 + bn * 80 + bf * 32;
            CPA(d0, sH); CPA(d0 + 16, sH + 16);
            CPC();
            CPW(1);
        } else {
            CPW(0);
        }
        __syncthreads();

        uint32_t bufB = smb + O_B0 + (kc & 1) * 20480 + bOff;
        #pragma unroll
        for (int ks = 0; ks < 2; ks++) {
            uint32_t ah[4];
            ldmx4(ah, aAddr + ks * 32);
            uint32_t bh[8][4];
            #pragma unroll
            for (int jt = 0; jt < 8; jt++)
                ldmx4(bh[jt], bufB + jt * 1280 + ks * 32);
            #pragma unroll
            for (int jt = 0; jt < 8; jt++) {
                mma16816(d[2 * jt], ah, bh[jt][0], bh[jt][1]);
                mma16816(d[2 * jt + 1], ah, bh[jt][2], bh[jt][3]);
            }
        }
    }
    __syncthreads();   // ldmatrix reads done; msm may overwrite GEMM bufs

    // ---- pass 1: bias+relu, stats, msm write, score partials (d dies here) ----
    const int r0 = rg * 16 + (lane >> 2), r1 = r0 + 8;
    const int cq = (lane & 3) * 2;
    float s0 = 0.f, q0 = 0.f, s1 = 0.f, q1 = 0.f;
    float p0[NH], p1[NH];
    #pragma unroll
    for (int h = 0; h < NH; h++) { p0[h] = 0.f; p1[h] = 0.f; }
    #pragma unroll
    for (int nt = 0; nt < 16; nt++) {
        int c = cg * 128 + nt * 8 + cq;
        float2 bb = *(float2*)&S[(O_BIP >> 2) + c];
        float x0 = fmaxf(d[nt][0] + bb.x, 0.f), x1 = fmaxf(d[nt][1] + bb.y, 0.f);
        float y0 = fmaxf(d[nt][2] + bb.x, 0.f), y1 = fmaxf(d[nt][3] + bb.y, 0.f);
        s0 += x0 + x1; q0 += x0 * x0 + x1 * x1;
        s1 += y0 + y1; q1 += y0 * y0 + y1 * y1;
        *(__half2*)(sm + O_MSM + (r0 * 264 + c) * 2) = __floats2half2_rn(x0, x1);
        *(__half2*)(sm + O_MSM + (r1 * 264 + c) * 2) = __floats2half2_rn(y0, y1);
        #pragma unroll
        for (int h = 0; h < NH; h++) {
            float2 qv = *(float2*)&S[(O_GQ >> 2) + h * 264 + c];
            p0[h] += x0 * qv.x + x1 * qv.y;
            p1[h] += y0 * qv.x + y1 * qv.y;
        }
    }
    #pragma unroll
    for (int o = 1; o <= 2; o <<= 1) {
        s0 += __shfl_xor_sync(~0u, s0, o); q0 += __shfl_xor_sync(~0u, q0, o);
        s1 += __shfl_xor_sync(~0u, s1, o); q1 += __shfl_xor_sync(~0u, q1, o);
        #pragma unroll
        for (int h = 0; h < NH; h++) {
            p0[h] += __shfl_xor_sync(~0u, p0[h], o);
            p1[h] += __shfl_xor_sync(~0u, p1[h], o);
        }
    }
    if ((lane & 3) == 0) {
        S[(O_ST >> 2) + r0 * 2 + cg] = s0; S[(O_ST >> 2) + 256 + r0 * 2 + cg] = q0;
        S[(O_ST >> 2) + r1 * 2 + cg] = s1; S[(O_ST >> 2) + 256 + r1 * 2 + cg] = q1;
        #pragma unroll
        for (int h = 0; h < NH; h++) {
            S[(O_SPC >> 2) + (r0 * 8 + h) * 2 + cg] = p0[h];
            S[(O_SPC >> 2) + (r1 * 8 + h) * 2 + cg] = p1[h];
        }
    }
    __syncthreads();

    // ---- score combine: sc = (rs*(P - mu*G) + QC) * ior ----
    for (int e = t; e < NH * 128; e += 512) {
        int h = e >> 7, rr = e & 127;
        float P = S[(O_SPC >> 2) + (rr * 8 + h) * 2] + S[(O_SPC >> 2) + (rr * 8 + h) * 2 + 1];
        float su = S[(O_ST >> 2) + rr * 2] + S[(O_ST >> 2) + rr * 2 + 1];
        float sq = S[(O_ST >> 2) + 256 + rr * 2] + S[(O_ST >> 2) + 256 + rr * 2 + 1];
        float mu = su * (1.f / C_);
        float rs = rsqrtf(sq * (1.f / C_) - mu * mu + EPS);
        if (h == 0) { S[(O_MU >> 2) + rr] = mu; S[(O_RS >> 2) + rr] = rs; }
        S[(O_WSM >> 2) + e] = (rs * (P - mu * S[(O_CG >> 2) + h]) + S[(O_CQC >> 2) + h])
                              * S[(O_IOR >> 2) + e];
    }
    __syncthreads();

    // ---- per-tile softmax; WSM <- w*rs; W, s2 per head ----
    if (wid < NH) {
        float v0 = S[(O_WSM >> 2) + wid * 128 + lane];
        float v1 = S[(O_WSM >> 2) + wid * 128 + 32 + lane];
        float v2 = S[(O_WSM >> 2) + wid * 128 + 64 + lane];
        float v3 = S[(O_WSM >> 2) + wid * 128 + 96 + lane];
        float mx = fmaxf(fmaxf(v0, v1), fmaxf(v2, v3));
        #pragma unroll
        for (int o = 16; o >= 1; o >>= 1) mx = fmaxf(mx, __shfl_xor_sync(~0u, mx, o));
        float e0 = __expf(v0 - mx), e1 = __expf(v1 - mx);
        float e2 = __expf(v2 - mx), e3 = __expf(v3 - mx);
        float rs0 = S[(O_RS >> 2) + lane],      mu0 = S[(O_MU >> 2) + lane];
        float rs1 = S[(O_RS >> 2) + 32 + lane], mu1 = S[(O_MU >> 2) + 32 + lane];
        float rs2 = S[(O_RS >> 2) + 64 + lane], mu2 = S[(O_MU >> 2) + 64 + lane];
        float rs3 = S[(O_RS >> 2) + 96 + lane], mu3 = S[(O_MU >> 2) + 96 + lane];
        S[(O_WSM >> 2) + wid * 128 + lane]      = e0 * rs0;
        S[(O_WSM >> 2) + wid * 128 + 32 + lane] = e1 * rs1;
        S[(O_WSM >> 2) + wid * 128 + 64 + lane] = e2 * rs2;
        S[(O_WSM >> 2) + wid * 128 + 96 + lane] = e3 * rs3;
        float es = (e0 + e1) + (e2 + e3);
        float s2 = e0 * rs0 * mu0 + e1 * rs1 * mu1 + e2 * rs2 * mu2 + e3 * rs3 * mu3;
        #pragma unroll
        for (int o = 16; o >= 1; o >>= 1) {
            es += __shfl_xor_sync(~0u, es, o);
            s2 += __shfl_xor_sync(~0u, s2, o);
        }
        if (lane == 0) {
            g_pmax[j * NH + wid] = mx;
            g_psum[j * NH + wid] = es;
            S[(O_CW >> 2) + wid] = es;
            S[(O_CS2 >> 2) + wid] = s2;
        }
    }
    __syncthreads();

    // ---- ctx partial: acc = sum_r (w*rs) * m^ ; out = g*(acc - s2) + be*W ----
    {
        const int c4 = t & 63, sl = t >> 6;
        float4 a8[NH];
        #pragma unroll
        for (int h = 0; h < NH; h++) a8[h] = make_float4(0.f, 0.f, 0.f, 0.f);
        for (int r = sl * 16; r < sl * 16 + 16; r++) {
            uint2 u = *(uint2*)(sm + O_MSM + (r * 264 + c4 * 4) * 2);
            float2 f01 = __half22float2(*(__half2*)&u.x);
            float2 f23 = __half22float2(*(__half2*)&u.y);
            #pragma unroll
            for (int h = 0; h < NH; h++) {
                float w = S[(O_WSM >> 2) + h * 128 + r];
                a8[h].x += w * f01.x; a8[h].y += w * f01.y;
                a8[h].z += w * f23.x; a8[h].w += w * f23.y;
            }
        }
        #pragma unroll
        for (int h = 0; h < NH; h++)
            *(float4*)&S[(O_SPC >> 2) + ((sl * 8 + h) * 64 + c4) * 4] = a8[h];
        __syncthreads();
        const int hh = t >> 6, cc = t & 63;
        float4 s4 = make_float4(0.f, 0.f, 0.f, 0.f);
        #pragma unroll
        for (int s2i = 0; s2i < 8; s2i++) {
            float4 v = *(float4*)&S[(O_SPC >> 2) + ((s2i * 8 + hh) * 64 + cc) * 4];
            s4.x += v.x; s4.y += v.y; s4.z += v.z; s4.w += v.w;
        }
        float4 gg = *(float4*)&S[(O_GIP >> 2) + cc * 4];
        float4 ee = *(float4*)&S[(O_BEI >> 2) + cc * 4];
        float sh = S[(O_CS2 >> 2) + hh], Wh = S[(O_CW >> 2) + hh];
        float4 outv;
        outv.x = gg.x * (s4.x - sh) + ee.x * Wh;
        outv.y = gg.y * (s4.y - sh) + ee.y * Wh;
        outv.z = gg.z * (s4.z - sh) + ee.z * Wh;
        outv.w = gg.w * (s4.w - sh) + ee.w * Wh;
        ((float4*)g_pctx)[(size_t)j * 512 + hh * 64 + cc] = outv;
    }
}

// ---- K2a: parallel softmax-combine, one block per (b,h), 1024 thr ----
__global__ void k2a() {
    __shared__ float pm[128], ps[128], ef[128], red[4], red2[4], cacc[4 * 256];
    const int b = blockIdx.x >> 3, h = blockIdx.x & 7;
    const int t = threadIdx.x, lane = t & 31;
    const int col = t & 255, sl = t >> 8;
    if (t < 128) {
        pm[t] = g_pmax[(b * 128 + t) * NH + h];
        ps[t] = g_psum[(b * 128 + t) * NH + h];
    }
    __syncthreads();
    if (t < 128) {
        float v = pm[t];
        #pragma unroll
        for (int o = 16; o >= 1; o >>= 1) v = fmaxf(v, __shfl_xor_sync(~0u, v, o));
        if (lane == 0) red[t >> 5] = v;
    }
    __syncthreads();
    float gmax = fmaxf(fmaxf(red[0], red[1]), fmaxf(red[2], red[3]));
    if (t < 128) ef[t] = __expf(pm[t] - gmax);
    __syncthreads();
    if (t < 128) {
        float v = ps[t] * ef[t];
        #pragma unroll
        for (int o = 16; o >= 1; o >>= 1) v += __shfl_xor_sync(~0u, v, o);
        if (lane == 0) red2[t >> 5] = v;
    }
    __syncthreads();
    float acc = 0.f;
    const float* p = g_pctx + ((size_t)(b * 128 + sl * 32) * NH + h) * C_ + col;
    #pragma unroll 4
    for (int ch = 0; ch < 32; ch++)
        acc += ef[sl * 32 + ch] * p[(size_t)ch * NH * C_];
    cacc[sl * 256 + col] = acc;
    __syncthreads();
    if (sl == 0) {
        float inv = 1.f / (red2[0] + red2[1] + red2[2] + red2[3]);
        float tot = cacc[col] + cacc[256 + col] + cacc[512 + col] + cacc[768 + col];
        g_ctxn[(b * NH + h) * C_ + col] = tot * inv;
    }
}

// ---- K2b: V-proj + residual + LN + FFN ----
__global__ void k2b(const float* __restrict__ query, const float* __restrict__ W_kv,
                    const float* __restrict__ b_kv, const float* __restrict__ g_f,
                    const float* __restrict__ be_f, const float* __restrict__ W1,
                    const float* __restrict__ b1, const float* __restrict__ W2,
                    const float* __restrict__ b2, float* __restrict__ out) {
    __shared__ float ctxn[NH * C_], xs[C_], hs[C_], us[FFN], red[8], red2[8];
    const int b = blockIdx.x, t = threadIdx.x;
    for (int i = t; i < NH * C_; i += 256) ctxn[i] = g_ctxn[b * NH * C_ + i];
    __syncthreads();
    {
        const int h = t >> 5;
        float a0 = 0.f, a1 = 0.f, a2 = 0.f, a3 = 0.f;
        #pragma unroll 8
        for (int c = 0; c < C_; c += 4) {
            a0 += ctxn[h * C_ + c] * W_kv[c * (2 * C_) + C_ + t];
            a1 += ctxn[h * C_ + c + 1] * W_kv[(c + 1) * (2 * C_) + C_ + t];
            a2 += ctxn[h * C_ + c + 2] * W_kv[(c + 2) * (2 * C_) + C_ + t];
            a3 += ctxn[h * C_ + c + 3] * W_kv[(c + 3) * (2 * C_) + C_ + t];
        }
        float x = b_kv[C_ + t] + (a0 + a1) + (a2 + a3) + query[b * C_ + t];
        xs[t] = x;
        float s = x, s2 = x * x;
        #pragma unroll
        for (int o = 16; o >= 1; o >>= 1) {
            s += __shfl_xor_sync(~0u, s, o);
            s2 += __shfl_xor_sync(~0u, s2, o);
        }
        if ((t & 31) == 0) { red[t >> 5] = s; red2[t >> 5] = s2; }
        __syncthreads();
        float su = 0.f, sq = 0.f;
        #pragma unroll
        for (int i = 0; i < 8; i++) { su += red[i]; sq += red2[i]; }
        float mean = su / C_, var = sq / C_ - mean * mean, rs = rsqrtf(var + EPS);
        hs[t] = (x - mean) * rs * g_f[t] + be_f[t];
    }
    __syncthreads();
    for (int f = t; f < FFN; f += 256) {
        float a0 = 0.f, a1 = 0.f, a2 = 0.f, a3 = 0.f;
        #pragma unroll 8
        for (int c = 0; c < C_; c += 4) {
            a0 += hs[c] * W1[c * FFN + f];
            a1 += hs[c + 1] * W1[(c + 1) * FFN + f];
            a2 += hs[c + 2] * W1[(c + 2) * FFN + f];
            a3 += hs[c + 3] * W1[(c + 3) * FFN + f];
        }
        float u = b1[f] + (a0 + a1) + (a2 + a3);
        us[f] = 0.5f * u * (1.f + erff(u * 0.70710678118654752f));
    }
    __syncthreads();
    {
        float a0 = 0.f, a1 = 0.f, a2 = 0.f, a3 = 0.f;
        #pragma unroll 8
        for (int f = 0; f < FFN; f += 4) {
            a0 += us[f] * W2[f * C_ + t];
            a1 += us[f + 1] * W2[(f + 1) * C_ + t];
            a2 += us[f + 2] * W2[(f + 2) * C_ + t];
            a3 += us[f + 3] * W2[(f + 3) * C_ + t];
        }
        out[b * C_ + t] = xs[t] + b2[t] + (a0 + a1) + (a2 + a3);
    }
}

extern "C" void kernel_launch(void* const* d_in, const int* in_sizes, int n_in,
                              void* d_out, int out_size) {
    const float* query = (const float*)d_in[0];
    const float* mem   = (const float*)d_in[1];
    const float* ior   = (const float*)d_in[2];
    const float* W_ip  = (const float*)d_in[3];
    const float* b_ip  = (const float*)d_in[4];
    const float* g_ip  = (const float*)d_in[5];
    const float* be_ip = (const float*)d_in[6];
    const float* W_q   = (const float*)d_in[7];
    const float* b_q   = (const float*)d_in[8];
    const float* W_kv  = (const float*)d_in[9];
    const float* b_kv  = (const float*)d_in[10];
    const float* g_q   = (const float*)d_in[11];
    const float* be_q  = (const float*)d_in[12];
    const float* g_f   = (const float*)d_in[13];
    const float* be_f  = (const float*)d_in[14];
    const float* W1    = (const float*)d_in[15];
    const float* b1    = (const float*)d_in[16];
    const float* W2    = (const float*)d_in[17];
    const float* b2    = (const float*)d_in[18];

    cudaFuncSetAttribute(k1, cudaFuncAttributeMaxDynamicSharedMemorySize, SM1);
    k0b<<<C_, C_>>>(W_ip);
    k0<<<B_, C_>>>(query, W_q, b_q, W_kv, b_kv, g_q, be_q, g_ip, be_ip);
    k1<<<JOBS, 512, SM1>>>(mem, ior, b_ip, g_ip, be_ip);
    k2a<<<B_ * NH, 1024>>>();
    k2b<<<B_, C_>>>(query, W_kv, b_kv, g_f, be_f, W1, b1, W2, b2, (float*)d_out);
}